// round 5
// baseline (speedup 1.0000x reference)
#include <cuda_runtime.h>
#include <cstdint>

#define D    512
#define NBAT 256
#define H    128
#define LDIM 64
#define NV   32000
#define G5   640          // 5*H
#define NH   (NBAT*H)     // 32768

// ---- persistent device scratch (allocation-free rule) ----
__device__ float g_hst[D * NBAT * H];     // 64 MB
__device__ float g_cst[D * NBAT * H];     // 64 MB
__device__ float g_table[(size_t)NV * G5];// 82 MB: emb@W[0:64] + b
__device__ int   g_lidx[D * NBAT];        // left-child step index, -1 = shift

__device__ __forceinline__ float sigf(float x) {
    return __fdividef(1.0f, 1.0f + __expf(-x));
}
__device__ __forceinline__ float tanhfast(float x) {
    return 1.0f - __fdividef(2.0f, __expf(2.0f * x) + 1.0f);
}

// ============================================================
// K_pre: grid (1000, 5).
//   y<4 : table tile  g_table[v][c] = emb[v]@W[:64] + b
//   y==4: block x==0 runs the lidx stack simulation (concurrent)
// ============================================================
__global__ __launch_bounds__(256) void k_pre(const float* __restrict__ emb,
                                             const float* __restrict__ W,
                                             const float* __restrict__ bias,
                                             const int* __restrict__ trans) {
    if (blockIdx.y == 4) {
        if (blockIdx.x != 0) return;
        int b = threadIdx.x;            // 256 threads = NBAT
        short st[D];
        int ptr = 0;
        for (int t = 0; t < D; t++) {
            int m = trans[t * NBAT + b];
            int lx = -1;
            if (m) lx = st[ptr - 2];
            int np = ptr - 2 * m;
            st[np] = (short)t;
            ptr = np + 1;
            g_lidx[t * NBAT + b] = lx;
        }
        return;
    }
    extern __shared__ float sm[];
    float* emb_s = sm;              // [64][33]
    float* W_sc  = sm + 64 * 33;    // [64][160]
    const int v0 = blockIdx.x * 32;
    const int c0 = blockIdx.y * 160;
    const int tid = threadIdx.x;

    for (int idx = tid; idx < 32 * 64; idx += 256) {
        int vv = idx >> 6, k = idx & 63;
        emb_s[k * 33 + vv] = emb[(v0 + vv) * LDIM + k];
    }
    for (int idx = tid; idx < 64 * 40; idx += 256) {
        int k = idx / 40, cq = idx % 40;
        float4 w4 = *reinterpret_cast<const float4*>(&W[k * G5 + c0 + cq * 4]);
        *reinterpret_cast<float4*>(&W_sc[k * 160 + cq * 4]) = w4;
    }
    __syncthreads();

    const int vg = tid & 7;
    const int cg = tid >> 3;
    float acc[4][5];
#pragma unroll
    for (int j = 0; j < 5; j++) {
        float bj = __ldg(&bias[c0 + cg * 5 + j]);
#pragma unroll
        for (int i = 0; i < 4; i++) acc[i][j] = bj;
    }
#pragma unroll 4
    for (int k = 0; k < 64; k++) {
        float x[4], w[5];
#pragma unroll
        for (int i = 0; i < 4; i++) x[i] = emb_s[k * 33 + vg * 4 + i];
#pragma unroll
        for (int j = 0; j < 5; j++) w[j] = W_sc[k * 160 + cg * 5 + j];
#pragma unroll
        for (int i = 0; i < 4; i++)
#pragma unroll
            for (int j = 0; j < 5; j++) acc[i][j] += x[i] * w[j];
    }
#pragma unroll
    for (int i = 0; i < 4; i++)
#pragma unroll
        for (int j = 0; j < 5; j++)
            g_table[(size_t)(v0 + vg * 4 + i) * G5 + c0 + cg * 5 + j] = acc[i][j];
}

// ============================================================
// Main: 16 clusters x 8 CTAs, 256 thr/CTA, 1 CTA/SM.
// Cross-CTA step sync = mbarrier handshake (NO barrier.cluster per step).
// ============================================================
#define XROW   20
#define XBUF   (256 * XROW)
#define GPROW  18
#define SM_WD  0
#define SM_X   (256 * 160)                 // 40960
#define SM_GP  (SM_X + 2 * XBUF)           // 51200
#define SM_LF  (SM_GP + 4 * 16 * 5 * GPROW)// 56960
#define SM_MB  (SM_LF + 128)               // 57088 (8B aligned)
#define SM_TOT ((SM_MB + 4) * 4)

__global__ __launch_bounds__(256, 1) __cluster_dims__(8, 1, 1)
void k_main(const int* __restrict__ labels,
            const float* __restrict__ W,
            const float* __restrict__ leaf,
            float* __restrict__ out) {
    extern __shared__ float sm[];
    float* Wd     = sm + SM_WD;       // [256][80] duplicated for f32x2
    float* Xbuf   = sm + SM_X;        // 2 x [256][XROW]
    float* Gp     = sm + SM_GP;
    float* leaf_s = sm + SM_LF;

    const int bx  = blockIdx.x;
    const int r   = bx & 7;
    const int B   = (bx >> 3) * 16;
    const int tid = threadIdx.x;
    const int r16 = r * 16;

    const uint32_t mb = (uint32_t)__cvta_generic_to_shared(sm + SM_MB);

    // roles
    const int b   = tid & 15;        // owned batch
    const int jk  = tid >> 4;        // owned dim / k-group
    const int q   = tid >> 6;        // GEMM k-quarter
    const int ww  = tid & 63;
    const int bg  = ww & 3;
    const int jj  = ww >> 2;

    // ---- prologue ----
    for (int idx = tid; idx < 256 * 80; idx += 256) {
        int k = idx / 80, cc = idx % 80;
        float w = __ldg(&W[(64 + k) * G5 + (cc >> 4) * H + r16 + (cc & 15)]);
        Wd[idx * 2]     = w;
        Wd[idx * 2 + 1] = w;
    }
    if (tid < 128) leaf_s[tid] = leaf[tid];
    if (tid == 0)
        asm volatile("mbarrier.init.shared.b64 [%0], %1;" :: "r"(mb), "r"(8) : "memory");
    __syncthreads();
    // mbarriers + SMEM visible cluster-wide before any arrive/push
    asm volatile("barrier.cluster.arrive.aligned;" ::: "memory");
    asm volatile("barrier.cluster.wait.aligned;" ::: "memory");

    // leafW: lw5[g] = sum_k leaf[k]*(Whl+Whr) for owned col (g, jk)
    float lw5[5];
#pragma unroll
    for (int g = 0; g < 5; g++) lw5[g] = 0.0f;
    for (int k = 0; k < 128; k++) {
        float lv = leaf_s[k];
#pragma unroll
        for (int g = 0; g < 5; g++)
            lw5[g] += lv * (Wd[(k * 80 + g * 16 + jk) * 2]
                          + Wd[((128 + k) * 80 + g * 16 + jk) * 2]);
    }

    // pipeline regs
    int liA  = __ldg(&g_lidx[B + b]);            // t=0
    int liB  = __ldg(&g_lidx[NBAT + B + b]);     // t=1
    int labB = __ldg(&labels[NBAT + B + b]);
    float tab5[5];
    {
        int labA = __ldg(&labels[B + b]);
#pragma unroll
        for (int g = 0; g < 5; g++)
            tab5[g] = __ldg(&g_table[(size_t)labA * G5 + g * H + r16 + jk]);
    }
    float cl = leaf_s[r16 + jk];
    float cprev = 0.0f;
    int cur = 0;

    for (int t = 0; t < D; t++) {
        float* Xc = Xbuf + cur * XBUF;
        float* Xn = Xbuf + (cur ^ 1) * XBUF;

        // ---- prefetch for t+1 ----
        float xl[8];
        bool redB = (liB >= 0);
        if (redB) {
            const float4* s4 = reinterpret_cast<const float4*>(
                &g_hst[(size_t)liB * NH + (B + b) * H + jk * 8]);
            float4 a = __ldcg(s4), c4 = __ldcg(s4 + 1);
            xl[0]=a.x; xl[1]=a.y; xl[2]=a.z; xl[3]=a.w;
            xl[4]=c4.x; xl[5]=c4.y; xl[6]=c4.z; xl[7]=c4.w;
        }
        float cln = redB
            ? __ldcg(&g_cst[(size_t)liB * NH + (B + b) * H + r16 + jk])
            : leaf_s[r16 + jk];
        float t5n[5];
#pragma unroll
        for (int g = 0; g < 5; g++)
            t5n[g] = __ldg(&g_table[(size_t)labB * G5 + g * H + r16 + jk]);
        const int t2 = (t + 2 < D) ? (t + 2) : (D - 1);
        const int liC  = __ldg(&g_lidx[t2 * NBAT + B + b]);
        const int labC = __ldg(&labels[t2 * NBAT + B + b]);

        // ---- GEMM on X[cur] (output used only for reduce batches) ----
        unsigned long long acc[2][5];
#pragma unroll
        for (int g = 0; g < 5; g++) { acc[0][g] = 0ULL; acc[1][g] = 0ULL; }
        {
            const float* xp = Xc + q * 64 * XROW + bg * 4;
            const unsigned long long* wp =
                reinterpret_cast<const unsigned long long*>(Wd) + q * 64 * 80 + jj;
#pragma unroll 4
            for (int k = 0; k < 64; k++) {
                ulonglong2 xv = *reinterpret_cast<const ulonglong2*>(xp + k * XROW);
                const unsigned long long* wr = wp + k * 80;
#pragma unroll
                for (int g = 0; g < 5; g++) {
                    unsigned long long w2 = wr[g * 16];
                    asm("fma.rn.f32x2 %0, %1, %2, %0;"
                        : "+l"(acc[0][g]) : "l"(xv.x), "l"(w2));
                    asm("fma.rn.f32x2 %0, %1, %2, %0;"
                        : "+l"(acc[1][g]) : "l"(xv.y), "l"(w2));
                }
            }
        }

        if (redB) {   // left half of X[next]
#pragma unroll
            for (int i = 0; i < 8; i++) Xn[(jk * 8 + i) * XROW + b] = xl[i];
        }
#pragma unroll
        for (int g = 0; g < 5; g++) {
            int row = ((q * 16 + jj) * 5 + g) * GPROW + bg * 4;
            *reinterpret_cast<unsigned long long*>(&Gp[row])     = acc[0][g];
            *reinterpret_cast<unsigned long long*>(&Gp[row + 2]) = acc[1][g];
        }
        __syncthreads();

        // ---- reduce + nonlinearity: thread owns (b, jk) ----
        {
            float gate[5];
            if (liA >= 0) {
#pragma unroll
                for (int g = 0; g < 5; g++) gate[g] = tab5[g];
#pragma unroll
                for (int q2 = 0; q2 < 4; q2++)
#pragma unroll
                    for (int g = 0; g < 5; g++)
                        gate[g] += Gp[((q2 * 16 + jk) * 5 + g) * GPROW + b];
            } else {
#pragma unroll
                for (int g = 0; g < 5; g++) gate[g] = tab5[g] + lw5[g];
            }
            float lf  = leaf_s[r16 + jk];
            float clv = (liA >= 0) ? cl    : lf;
            float crv = (liA >= 0) ? cprev : lf;
            float c = sigf(gate[0]) * tanhfast(gate[4])
                    + sigf(gate[1]) * clv + sigf(gate[2]) * crv;
            float h = sigf(gate[3]) * tanhfast(c);
            cprev = c;
            const size_t o = (size_t)t * NH + (B + b) * H + r16 + jk;
            g_hst[o] = h;
            g_cst[o] = c;
            // push h into siblings' X[next] right half (only if t+1 reduces b)
            if (redB && t < D - 1) {
                uint32_t xaddr = (uint32_t)__cvta_generic_to_shared(
                    &Xn[(128 + r16 + jk) * XROW + b]);
#pragma unroll
                for (int cta = 0; cta < 8; cta++) {
                    uint32_t rem;
                    asm("mapa.shared::cluster.u32 %0, %1, %2;"
                        : "=r"(rem) : "r"(xaddr), "r"(cta));
                    asm volatile("st.shared::cluster.f32 [%0], %1;"
                                 :: "r"(rem), "f"(h) : "memory");
                }
            }
            if (t == D - 1) {
                out[(B + b) * H + r16 + jk]      = c;   // cells
                out[NH + (B + b) * H + r16 + jk] = h;   // embeddings
            }
        }
        __syncthreads();

        // ---- handshake: release own step-t results, acquire siblings' ----
        if (t < D - 1) {
            if (tid < 8) {
                asm volatile("fence.acq_rel.cluster;" ::: "memory");
                uint32_t rem;
                asm("mapa.shared::cluster.u32 %0, %1, %2;"
                    : "=r"(rem) : "r"(mb), "r"(tid));
                asm volatile("mbarrier.arrive.release.cluster.shared::cluster.b64 _, [%0];"
                             :: "r"(rem) : "memory");
            }
            const unsigned par = t & 1;
            asm volatile(
                "{\n\t"
                ".reg .pred P;\n\t"
                "WL%=:\n\t"
                "mbarrier.try_wait.parity.acquire.cluster.shared::cta.b64 P, [%0], %1, 0x989680;\n\t"
                "@P bra WD%=;\n\t"
                "bra WL%=;\n\t"
                "WD%=:\n\t"
                "}" :: "r"(mb), "r"(par) : "memory");
        }

        liA = liB; liB = liC; labB = labC;
        cl = cln;
#pragma unroll
        for (int g = 0; g < 5; g++) tab5[g] = t5n[g];
        cur ^= 1;
    }

    // keep cluster SMEM alive until all in-flight remote ops land
    asm volatile("barrier.cluster.arrive.aligned;" ::: "memory");
    asm volatile("barrier.cluster.wait.aligned;" ::: "memory");
}

// ============================================================
extern "C" void kernel_launch(void* const* d_in, const int* in_sizes, int n_in,
                              void* d_out, int out_size) {
    const int*   trans  = (const int*)d_in[0];
    const int*   labels = (const int*)d_in[1];
    const float* emb    = (const float*)d_in[2];
    const float* W      = (const float*)d_in[3];
    const float* bias   = (const float*)d_in[4];
    const float* leaf   = (const float*)d_in[5];
    float* out = (float*)d_out;

    cudaFuncSetAttribute(k_pre, cudaFuncAttributeMaxDynamicSharedMemorySize,
                         64 * 33 * 4 + 64 * 160 * 4);
    cudaFuncSetAttribute(k_main, cudaFuncAttributeMaxDynamicSharedMemorySize,
                         SM_TOT);

    dim3 pgrid(NV / 32, 5);   // y=4 row runs the lidx sim concurrently
    k_pre<<<pgrid, 256, 64 * 33 * 4 + 64 * 160 * 4>>>(emb, W, bias, trans);
    k_main<<<128, 256, SM_TOT>>>(labels, W, leaf, out);
}

// round 6
// speedup vs baseline: 1.0667x; 1.0667x over previous
#include <cuda_runtime.h>
#include <cstdint>

#define D    512
#define NBAT 256
#define H    128
#define LDIM 64
#define NV   32000
#define G5   640          // 5*H
#define NH   (NBAT*H)     // 32768

// ---- persistent device scratch (allocation-free rule) ----
__device__ float g_hst[D * NBAT * H];     // 64 MB
__device__ float g_cst[D * NBAT * H];     // 64 MB
__device__ float g_table[(size_t)NV * G5];// 82 MB: emb@W[0:64] + b
__device__ int   g_lidx[D * NBAT];        // left-child step index, -1 = shift

__device__ __forceinline__ float sigf(float x) {
    return __fdividef(1.0f, 1.0f + __expf(-x));
}
__device__ __forceinline__ float tanhfast(float x) {
    return 1.0f - __fdividef(2.0f, __expf(2.0f * x) + 1.0f);
}

// ============================================================
// K_pre: grid (1000, 5).
//   y<4 : table tile  g_table[v][c] = emb[v]@W[:64] + b
//   y==4: block x==0 runs the lidx stack simulation
// ============================================================
__global__ __launch_bounds__(256) void k_pre(const float* __restrict__ emb,
                                             const float* __restrict__ W,
                                             const float* __restrict__ bias,
                                             const int* __restrict__ trans) {
    if (blockIdx.y == 4) {
        if (blockIdx.x != 0) return;
        int b = threadIdx.x;
        short st[D];
        int ptr = 0;
        for (int t = 0; t < D; t++) {
            int m = trans[t * NBAT + b];
            int lx = -1;
            if (m) lx = st[ptr - 2];
            int np = ptr - 2 * m;
            st[np] = (short)t;
            ptr = np + 1;
            g_lidx[t * NBAT + b] = lx;
        }
        return;
    }
    extern __shared__ float sm[];
    float* emb_s = sm;              // [64][33]
    float* W_sc  = sm + 64 * 33;    // [64][160]
    const int v0 = blockIdx.x * 32;
    const int c0 = blockIdx.y * 160;
    const int tid = threadIdx.x;

    for (int idx = tid; idx < 32 * 64; idx += 256) {
        int vv = idx >> 6, k = idx & 63;
        emb_s[k * 33 + vv] = emb[(v0 + vv) * LDIM + k];
    }
    for (int idx = tid; idx < 64 * 40; idx += 256) {
        int k = idx / 40, cq = idx % 40;
        float4 w4 = *reinterpret_cast<const float4*>(&W[k * G5 + c0 + cq * 4]);
        *reinterpret_cast<float4*>(&W_sc[k * 160 + cq * 4]) = w4;
    }
    __syncthreads();

    const int vg = tid & 7;
    const int cg = tid >> 3;
    float acc[4][5];
#pragma unroll
    for (int j = 0; j < 5; j++) {
        float bj = __ldg(&bias[c0 + cg * 5 + j]);
#pragma unroll
        for (int i = 0; i < 4; i++) acc[i][j] = bj;
    }
#pragma unroll 4
    for (int k = 0; k < 64; k++) {
        float x[4], w[5];
#pragma unroll
        for (int i = 0; i < 4; i++) x[i] = emb_s[k * 33 + vg * 4 + i];
#pragma unroll
        for (int j = 0; j < 5; j++) w[j] = W_sc[k * 160 + cg * 5 + j];
#pragma unroll
        for (int i = 0; i < 4; i++)
#pragma unroll
            for (int j = 0; j < 5; j++) acc[i][j] += x[i] * w[j];
    }
#pragma unroll
    for (int i = 0; i < 4; i++)
#pragma unroll
        for (int j = 0; j < 5; j++)
            g_table[(size_t)(v0 + vg * 4 + i) * G5 + c0 + cg * 5 + j] = acc[i][j];
}

// ============================================================
// Main: 16 clusters x 8 CTAs, 256 thr/CTA, 1 CTA/SM.
// Per-step sync: mbarrier arrive.release.cluster / try_wait.acquire
// (NO explicit cluster fence -> no per-step CCTL.IVALL, hopefully).
// All mutable global traffic is .cg (L1-bypass) so relaxed L1 is safe.
// ============================================================
#define XROW   20
#define XBUF   (256 * XROW)
#define GPROW  18
#define SM_WD  0
#define SM_X   (256 * 160)                 // 40960
#define SM_GP  (SM_X + 2 * XBUF)           // 51200
#define SM_LF  (SM_GP + 4 * 16 * 5 * GPROW)// 56960
#define SM_HS  (SM_LF + 128)               // h stage [16][17]
#define SM_CS  (SM_HS + 16 * 17)           // c stage [16][17]
#define SM_MB  (SM_CS + 16 * 17 + 2)       // 8B-aligned mbarrier
#define SM_TOT ((SM_MB + 4) * 4)

__global__ __launch_bounds__(256, 1) __cluster_dims__(8, 1, 1)
void k_main(const int* __restrict__ labels,
            const float* __restrict__ W,
            const float* __restrict__ leaf,
            float* __restrict__ out) {
    extern __shared__ float sm[];
    float* Wd     = sm + SM_WD;       // [256][80] duplicated for f32x2
    float* Xbuf   = sm + SM_X;        // 2 x [256][XROW]
    float* Gp     = sm + SM_GP;
    float* leaf_s = sm + SM_LF;
    float* hstage = sm + SM_HS;
    float* cstage = sm + SM_CS;

    const int bx  = blockIdx.x;
    const int r   = bx & 7;
    const int B   = (bx >> 3) * 16;
    const int tid = threadIdx.x;
    const int r16 = r * 16;

    const uint32_t mb = (uint32_t)__cvta_generic_to_shared(sm + SM_MB);

    // roles
    const int b   = tid & 15;        // owned batch
    const int jk  = tid >> 4;        // owned dim / k-group
    const int q   = tid >> 6;        // GEMM k-quarter
    const int ww  = tid & 63;
    const int bg  = ww & 3;
    const int jj  = ww >> 2;
    // coalesced-store roles (transposed)
    const int jk2 = tid & 15;
    const int b2  = tid >> 4;

    // ---- prologue ----
    for (int idx = tid; idx < 256 * 80; idx += 256) {
        int k = idx / 80, cc = idx % 80;
        float w = __ldg(&W[(64 + k) * G5 + (cc >> 4) * H + r16 + (cc & 15)]);
        Wd[idx * 2]     = w;
        Wd[idx * 2 + 1] = w;
    }
    if (tid < 128) leaf_s[tid] = leaf[tid];
    if (tid == 0)
        asm volatile("mbarrier.init.shared.b64 [%0], %1;" :: "r"(mb), "r"(8) : "memory");
    __syncthreads();
    // one-time: make mbarriers + SMEM visible cluster-wide
    asm volatile("barrier.cluster.arrive.aligned;" ::: "memory");
    asm volatile("barrier.cluster.wait.aligned;" ::: "memory");

    // leafW: lw5[g] = sum_k leaf[k]*(Whl+Whr) for owned col (g, jk)
    float lw5[5];
#pragma unroll
    for (int g = 0; g < 5; g++) lw5[g] = 0.0f;
    for (int k = 0; k < 128; k++) {
        float lv = leaf_s[k];
#pragma unroll
        for (int g = 0; g < 5; g++)
            lw5[g] += lv * (Wd[(k * 80 + g * 16 + jk) * 2]
                          + Wd[((128 + k) * 80 + g * 16 + jk) * 2]);
    }

    // pipeline regs
    int liA  = __ldg(&g_lidx[B + b]);            // t=0
    int liB  = __ldg(&g_lidx[NBAT + B + b]);     // t=1
    int labB = __ldg(&labels[NBAT + B + b]);
    float tab5[5];
    {
        int labA = __ldg(&labels[B + b]);
#pragma unroll
        for (int g = 0; g < 5; g++)
            tab5[g] = __ldg(&g_table[(size_t)labA * G5 + g * H + r16 + jk]);
    }
    float cl = leaf_s[r16 + jk];
    float cprev = 0.0f;
    int cur = 0;

    for (int t = 0; t < D; t++) {
        float* Xc = Xbuf + cur * XBUF;
        float* Xn = Xbuf + (cur ^ 1) * XBUF;

        // ---- prefetch for t+1 ----
        float xl[8];
        bool redB = (liB >= 0);
        if (redB) {
            const float4* s4 = reinterpret_cast<const float4*>(
                &g_hst[(size_t)liB * NH + (B + b) * H + jk * 8]);
            float4 a = __ldcg(s4), c4 = __ldcg(s4 + 1);
            xl[0]=a.x; xl[1]=a.y; xl[2]=a.z; xl[3]=a.w;
            xl[4]=c4.x; xl[5]=c4.y; xl[6]=c4.z; xl[7]=c4.w;
        }
        float cln = redB
            ? __ldcg(&g_cst[(size_t)liB * NH + (B + b) * H + r16 + jk])
            : leaf_s[r16 + jk];
        float t5n[5];
#pragma unroll
        for (int g = 0; g < 5; g++)
            t5n[g] = __ldg(&g_table[(size_t)labB * G5 + g * H + r16 + jk]);
        const int t2 = (t + 2 < D) ? (t + 2) : (D - 1);
        const int liC  = __ldg(&g_lidx[t2 * NBAT + B + b]);
        const int labC = __ldg(&labels[t2 * NBAT + B + b]);

        // ---- GEMM on X[cur] (used only for reduce batches) ----
        unsigned long long acc[2][5];
#pragma unroll
        for (int g = 0; g < 5; g++) { acc[0][g] = 0ULL; acc[1][g] = 0ULL; }
        {
            const float* xp = Xc + q * 64 * XROW + bg * 4;
            const unsigned long long* wp =
                reinterpret_cast<const unsigned long long*>(Wd) + q * 64 * 80 + jj;
#pragma unroll 4
            for (int k = 0; k < 64; k++) {
                ulonglong2 xv = *reinterpret_cast<const ulonglong2*>(xp + k * XROW);
                const unsigned long long* wr = wp + k * 80;
#pragma unroll
                for (int g = 0; g < 5; g++) {
                    unsigned long long w2 = wr[g * 16];
                    asm("fma.rn.f32x2 %0, %1, %2, %0;"
                        : "+l"(acc[0][g]) : "l"(xv.x), "l"(w2));
                    asm("fma.rn.f32x2 %0, %1, %2, %0;"
                        : "+l"(acc[1][g]) : "l"(xv.y), "l"(w2));
                }
            }
        }

        if (redB) {   // left half of X[next]
#pragma unroll
            for (int i = 0; i < 8; i++) Xn[(jk * 8 + i) * XROW + b] = xl[i];
        }
#pragma unroll
        for (int g = 0; g < 5; g++) {
            int row = ((q * 16 + jj) * 5 + g) * GPROW + bg * 4;
            *reinterpret_cast<unsigned long long*>(&Gp[row])     = acc[0][g];
            *reinterpret_cast<unsigned long long*>(&Gp[row + 2]) = acc[1][g];
        }
        __syncthreads();

        // ---- reduce + nonlinearity: thread owns (b, jk) ----
        {
            float gate[5];
            if (liA >= 0) {
#pragma unroll
                for (int g = 0; g < 5; g++) gate[g] = tab5[g];
#pragma unroll
                for (int q2 = 0; q2 < 4; q2++)
#pragma unroll
                    for (int g = 0; g < 5; g++)
                        gate[g] += Gp[((q2 * 16 + jk) * 5 + g) * GPROW + b];
            } else {
#pragma unroll
                for (int g = 0; g < 5; g++) gate[g] = tab5[g] + lw5[g];
            }
            float lf  = leaf_s[r16 + jk];
            float clv = (liA >= 0) ? cl    : lf;
            float crv = (liA >= 0) ? cprev : lf;
            float c = sigf(gate[0]) * tanhfast(gate[4])
                    + sigf(gate[1]) * clv + sigf(gate[2]) * crv;
            float h = sigf(gate[3]) * tanhfast(c);
            cprev = c;
            hstage[b * 17 + jk] = h;
            cstage[b * 17 + jk] = c;
            // push h into siblings' X[next] right half (only if t+1 reduces b)
            if (redB && t < D - 1) {
                uint32_t xaddr = (uint32_t)__cvta_generic_to_shared(
                    &Xn[(128 + r16 + jk) * XROW + b]);
#pragma unroll
                for (int cta = 0; cta < 8; cta++) {
                    uint32_t rem;
                    asm("mapa.shared::cluster.u32 %0, %1, %2;"
                        : "=r"(rem) : "r"(xaddr), "r"(cta));
                    asm volatile("st.shared::cluster.f32 [%0], %1;"
                                 :: "r"(rem), "f"(h) : "memory");
                }
            }
        }
        __syncthreads();

        // ---- coalesced state writeback (.cg, transposed roles) ----
        {
            float hv = hstage[b2 * 17 + jk2];
            float cv = cstage[b2 * 17 + jk2];
            const size_t o = (size_t)t * NH + (B + b2) * H + r16 + jk2;
            __stcg(&g_hst[o], hv);
            __stcg(&g_cst[o], cv);
            if (t == D - 1) {
                out[(B + b2) * H + r16 + jk2]      = cv;   // cells
                out[NH + (B + b2) * H + r16 + jk2] = hv;   // embeddings
            }
        }

        // ---- handshake: release own step-t results, acquire siblings' ----
        if (t < D - 1) {
            if (tid < 8) {
                uint32_t rem;
                asm("mapa.shared::cluster.u32 %0, %1, %2;"
                    : "=r"(rem) : "r"(mb), "r"(tid));
                asm volatile("mbarrier.arrive.release.cluster.shared::cluster.b64 _, [%0];"
                             :: "r"(rem) : "memory");
            }
            const unsigned par = t & 1;
            asm volatile(
                "{\n\t"
                ".reg .pred P;\n\t"
                "WL%=:\n\t"
                "mbarrier.try_wait.parity.acquire.cluster.shared::cta.b64 P, [%0], %1, 0x989680;\n\t"
                "@P bra WD%=;\n\t"
                "bra WL%=;\n\t"
                "WD%=:\n\t"
                "}" :: "r"(mb), "r"(par) : "memory");
        }

        liA = liB; liB = liC; labB = labC;
        cl = cln;
#pragma unroll
        for (int g = 0; g < 5; g++) tab5[g] = t5n[g];
        cur ^= 1;
    }

    // keep cluster SMEM alive until all in-flight remote ops land
    asm volatile("barrier.cluster.arrive.aligned;" ::: "memory");
    asm volatile("barrier.cluster.wait.aligned;" ::: "memory");
}

// ============================================================
extern "C" void kernel_launch(void* const* d_in, const int* in_sizes, int n_in,
                              void* d_out, int out_size) {
    const int*   trans  = (const int*)d_in[0];
    const int*   labels = (const int*)d_in[1];
    const float* emb    = (const float*)d_in[2];
    const float* W      = (const float*)d_in[3];
    const float* bias   = (const float*)d_in[4];
    const float* leaf   = (const float*)d_in[5];
    float* out = (float*)d_out;

    cudaFuncSetAttribute(k_pre, cudaFuncAttributeMaxDynamicSharedMemorySize,
                         64 * 33 * 4 + 64 * 160 * 4);
    cudaFuncSetAttribute(k_main, cudaFuncAttributeMaxDynamicSharedMemorySize,
                         SM_TOT);

    dim3 pgrid(NV / 32, 5);
    k_pre<<<pgrid, 256, 64 * 33 * 4 + 64 * 160 * 4>>>(emb, W, bias, trans);
    k_main<<<128, 256, SM_TOT>>>(labels, W, leaf, out);
}

// round 8
// speedup vs baseline: 1.7937x; 1.6815x over previous
#include <cuda_runtime.h>
#include <cstdint>

#define D    512
#define NBAT 256
#define H    128
#define LDIM 64
#define NV   32000
#define G5   640          // 5*H
#define NH   (NBAT*H)     // 32768

// ---- persistent device scratch (allocation-free rule) ----
__device__ float g_hst[D * NBAT * H];     // 64 MB
__device__ float g_cst[D * NBAT * H];     // 64 MB
__device__ float g_table[(size_t)NV * G5];// 82 MB: emb@W[0:64] + b
__device__ int   g_lidx[D * NBAT];        // left-child step index, -1 = shift

__device__ __forceinline__ float sigf(float x) {
    return __fdividef(1.0f, 1.0f + __expf(-x));
}
__device__ __forceinline__ float tanhfast(float x) {
    return 1.0f - __fdividef(2.0f, __expf(2.0f * x) + 1.0f);
}
__device__ __forceinline__ float ull_lo(unsigned long long v) {
    return __uint_as_float((unsigned)(v & 0xffffffffull));
}
__device__ __forceinline__ float ull_hi(unsigned long long v) {
    return __uint_as_float((unsigned)(v >> 32));
}

// ============================================================
// K_pre: grid (1000, 5). y<4: table tiles; y==4,x==0: lidx sim.
// ============================================================
__global__ __launch_bounds__(256) void k_pre(const float* __restrict__ emb,
                                             const float* __restrict__ W,
                                             const float* __restrict__ bias,
                                             const int* __restrict__ trans) {
    if (blockIdx.y == 4) {
        if (blockIdx.x != 0) return;
        int b = threadIdx.x;
        short st[D];
        int ptr = 0;
        for (int t = 0; t < D; t++) {
            int m = trans[t * NBAT + b];
            int lx = -1;
            if (m) lx = st[ptr - 2];
            int np = ptr - 2 * m;
            st[np] = (short)t;
            ptr = np + 1;
            g_lidx[t * NBAT + b] = lx;
        }
        return;
    }
    extern __shared__ float sm[];
    float* emb_s = sm;              // [64][33]
    float* W_sc  = sm + 64 * 33;    // [64][160]
    const int v0 = blockIdx.x * 32;
    const int c0 = blockIdx.y * 160;
    const int tid = threadIdx.x;

    for (int idx = tid; idx < 32 * 64; idx += 256) {
        int vv = idx >> 6, k = idx & 63;
        emb_s[k * 33 + vv] = emb[(v0 + vv) * LDIM + k];
    }
    for (int idx = tid; idx < 64 * 40; idx += 256) {
        int k = idx / 40, cq = idx % 40;
        float4 w4 = *reinterpret_cast<const float4*>(&W[k * G5 + c0 + cq * 4]);
        *reinterpret_cast<float4*>(&W_sc[k * 160 + cq * 4]) = w4;
    }
    __syncthreads();

    const int vg = tid & 7;
    const int cg = tid >> 3;
    float acc[4][5];
#pragma unroll
    for (int j = 0; j < 5; j++) {
        float bj = __ldg(&bias[c0 + cg * 5 + j]);
#pragma unroll
        for (int i = 0; i < 4; i++) acc[i][j] = bj;
    }
#pragma unroll 4
    for (int k = 0; k < 64; k++) {
        float x[4], w[5];
#pragma unroll
        for (int i = 0; i < 4; i++) x[i] = emb_s[k * 33 + vg * 4 + i];
#pragma unroll
        for (int j = 0; j < 5; j++) w[j] = W_sc[k * 160 + cg * 5 + j];
#pragma unroll
        for (int i = 0; i < 4; i++)
#pragma unroll
            for (int j = 0; j < 5; j++) acc[i][j] += x[i] * w[j];
    }
#pragma unroll
    for (int i = 0; i < 4; i++)
#pragma unroll
        for (int j = 0; j < 5; j++)
            g_table[(size_t)(v0 + vg * 4 + i) * G5 + c0 + cg * 5 + j] = acc[i][j];
}

// ============================================================
// Main: 32 active clusters of 4 CTAs (grid 148, 5 dummy clusters).
// Cluster owns 8 batch; CTA rank r owns hdims [32r, 32r+32).
// Thread (b, jj) owns all 5 gates of (b, r32+jj). X[b][k] row-major.
// h(t) pushed UNCONDITIONALLY into all 4 CTAs' X[next] right half
// (fixes R7: shift-at-t / reduce-at-t+1 needs h(t-1) in X[t]).
// ============================================================
#define XK     260
#define WROW   260
#define XBUF   (8 * XK)                      // 2080 floats per buffer
#define SM_WT  0                             // 160*260 = 41600
#define SM_X   41600                         // 2*2080 = 4160
#define SM_LF  45760                         // 128
#define SM_HS  45888                         // 8*33 = 264
#define SM_CS  46152                         // 264
#define SM_MB  46416                         // 2 (8B aligned)
#define SM_TOT ((46418) * 4)

__global__ __launch_bounds__(256, 1) __cluster_dims__(4, 1, 1)
void k_main(const int* __restrict__ labels,
            const float* __restrict__ W,
            const float* __restrict__ leaf,
            float* __restrict__ out) {
    const int bx = blockIdx.x;
    if ((bx >> 2) >= 32) return;   // dummy clusters (grid padded to 148)

    extern __shared__ float sm[];
    float* W_T    = sm + SM_WT;    // [160][260]
    float* Xbuf   = sm + SM_X;     // 2 x [8][260]
    float* leaf_s = sm + SM_LF;
    float* hstage = sm + SM_HS;    // [8][33]
    float* cstage = sm + SM_CS;

    const int r   = bx & 3;
    const int B   = (bx >> 2) * 8;
    const int tid = threadIdx.x;
    const int r32 = r * 32;
    const uint32_t mb = (uint32_t)__cvta_generic_to_shared(sm + SM_MB);
    const uint32_t xbase = (uint32_t)__cvta_generic_to_shared(Xbuf);

    // roles
    const int b   = tid & 7;       // GEMM/nonlin batch
    const int jj  = tid >> 3;      // hdim within slice (0..31)
    const int b2  = tid >> 5;      // cp.async / writeback batch
    const int s2  = tid & 31;      // 16B segment / hdim col

    // ---- prologue: W_T[c][k] = W[64+k][ (c>>5)*H + r32 + (c&31) ] ----
    for (int k = 0; k < 256; k++) {
        if (tid < 160) {
            int g = tid >> 5, cc = tid & 31;
            W_T[tid * WROW + k] = __ldg(&W[(64 + k) * G5 + g * H + r32 + cc]);
        }
    }
    if (tid < 128) leaf_s[tid] = leaf[tid];
    if (tid == 0)
        asm volatile("mbarrier.init.shared.b64 [%0], %1;" :: "r"(mb), "r"(4) : "memory");
    __syncthreads();
    asm volatile("barrier.cluster.arrive.aligned;" ::: "memory");
    asm volatile("barrier.cluster.wait.aligned;" ::: "memory");

    // leafW: lw5[g] = sum_k leaf[k]*(W_hl + W_hr) for col (g, r32+jj)
    float lw5[5];
#pragma unroll
    for (int g = 0; g < 5; g++) lw5[g] = 0.0f;
    for (int k = 0; k < 128; k++) {
        float lv = leaf_s[k];
#pragma unroll
        for (int g = 0; g < 5; g++)
            lw5[g] += lv * (W_T[(g * 32 + jj) * WROW + k]
                          + W_T[(g * 32 + jj) * WROW + 128 + k]);
    }

    // schedule regs
    int liA  = __ldg(&g_lidx[B + b]);            // t=0 (shift)
    int liB  = __ldg(&g_lidx[NBAT + B + b]);     // t=1
    int labB = __ldg(&labels[NBAT + B + b]);
    float tab5[5];
    {
        int labA = __ldg(&labels[B + b]);
#pragma unroll
        for (int g = 0; g < 5; g++)
            tab5[g] = __ldg(&g_table[(size_t)labA * G5 + g * H + r32 + jj]);
    }
    float cl = leaf_s[r32 + jj];
    float cprev = 0.0f;
    int cur = 0;

    for (int t = 0; t < D; t++) {
        __syncthreads();   // X[cur] ready (cp.async waited, DSMEM acquired)
        float* Xc = Xbuf + cur * XBUF;
        const int nxt = cur ^ 1;

        float cln = 0.0f, t5n[5];
        int liC = 0, labC = 0;
        if (t < D - 1) {
            // ---- prefetch t+1 (per-thread scalars) ----
            bool redB = (liB >= 0);
            cln = redB
                ? ((liB == t - 1) ? cprev
                   : __ldcg(&g_cst[(size_t)liB * NH + (B + b) * H + r32 + jj]))
                : leaf_s[r32 + jj];
#pragma unroll
            for (int g = 0; g < 5; g++)
                t5n[g] = __ldg(&g_table[(size_t)labB * G5 + g * H + r32 + jj]);
            const int t2 = (t + 2 < D) ? (t + 2) : (D - 1);
            liC  = __ldg(&g_lidx[t2 * NBAT + B + b]);
            labC = __ldg(&labels[t2 * NBAT + B + b]);

            // ---- left-half X[next] (roles b2, s2) ----
            int li2 = __ldg(&g_lidx[(t + 1) * NBAT + B + b2]);
            if (li2 >= 0) {
                uint32_t dst = xbase + (nxt * XBUF + b2 * XK + s2 * 4) * 4;
                if (li2 == t - 1) {
                    // h(t-1) lives in Xc right half (always pushed now)
                    float4 v = *reinterpret_cast<const float4*>(
                        &Xc[b2 * XK + 128 + s2 * 4]);
                    *reinterpret_cast<float4*>(
                        &Xbuf[nxt * XBUF + b2 * XK + s2 * 4]) = v;
                } else {
                    const float* src = &g_hst[(size_t)li2 * NH + (B + b2) * H + s2 * 4];
                    asm volatile("cp.async.cg.shared.global [%0], [%1], 16;"
                                 :: "r"(dst), "l"(src) : "memory");
                }
            }
            asm volatile("cp.async.commit_group;" ::: "memory");
        }

        // ---- GEMM: thread (b, jj) accumulates 5 gates over full K=256 ----
        unsigned long long acc[5];
#pragma unroll
        for (int g = 0; g < 5; g++) acc[g] = 0ULL;
        {
            const ulonglong2* xp = reinterpret_cast<const ulonglong2*>(Xc + b * XK);
            const ulonglong2* wp =
                reinterpret_cast<const ulonglong2*>(W_T + jj * WROW);
#pragma unroll 8
            for (int p = 0; p < 64; p++) {
                ulonglong2 xv = xp[p];
#pragma unroll
                for (int g = 0; g < 5; g++) {
                    ulonglong2 wv = wp[p + g * 2080];   // g stride: 32*260/4 ull2
                    asm("fma.rn.f32x2 %0, %1, %2, %0;"
                        : "+l"(acc[g]) : "l"(xv.x), "l"(wv.x));
                    asm("fma.rn.f32x2 %0, %1, %2, %0;"
                        : "+l"(acc[g]) : "l"(xv.y), "l"(wv.y));
                }
            }
        }

        // ---- nonlinearity (fully thread-local) ----
        {
            float gate[5];
            if (liA >= 0) {
#pragma unroll
                for (int g = 0; g < 5; g++)
                    gate[g] = tab5[g] + ull_lo(acc[g]) + ull_hi(acc[g]);
            } else {
#pragma unroll
                for (int g = 0; g < 5; g++) gate[g] = tab5[g] + lw5[g];
            }
            float lf  = leaf_s[r32 + jj];
            float clv = (liA >= 0) ? cl    : lf;
            float crv = (liA >= 0) ? cprev : lf;
            float c = sigf(gate[0]) * tanhfast(gate[4])
                    + sigf(gate[1]) * clv + sigf(gate[2]) * crv;
            float h = sigf(gate[3]) * tanhfast(c);
            cprev = c;
            hstage[b * 33 + jj] = h;
            cstage[b * 33 + jj] = c;
            // UNCONDITIONAL DSMEM push: h -> all 4 CTAs' X[next] right half
            if (t < D - 1) {
                uint32_t xaddr = xbase + (nxt * XBUF + b * XK + 128 + r32 + jj) * 4;
#pragma unroll
                for (int cta = 0; cta < 4; cta++) {
                    uint32_t rem;
                    asm("mapa.shared::cluster.u32 %0, %1, %2;"
                        : "=r"(rem) : "r"(xaddr), "r"(cta));
                    asm volatile("st.shared::cluster.f32 [%0], %1;"
                                 :: "r"(rem), "f"(h) : "memory");
                }
            }
        }
        __syncthreads();   // pushes + stage complete CTA-wide

        // ---- handshake ----
        if (t < D - 1) {
            if (tid < 4) {
                uint32_t rem;
                asm("mapa.shared::cluster.u32 %0, %1, %2;"
                    : "=r"(rem) : "r"(mb), "r"(tid));
                asm volatile("mbarrier.arrive.release.cluster.shared::cluster.b64 _, [%0];"
                             :: "r"(rem) : "memory");
            }
            const unsigned par = t & 1;
            asm volatile(
                "{\n\t"
                ".reg .pred P;\n\t"
                "WL%=:\n\t"
                "mbarrier.try_wait.parity.acquire.cluster.shared::cta.b64 P, [%0], %1, 0x989680;\n\t"
                "@P bra WD%=;\n\t"
                "bra WL%=;\n\t"
                "WD%=:\n\t"
                "}" :: "r"(mb), "r"(par) : "memory");
            asm volatile("cp.async.wait_group 0;" ::: "memory");
        }

        // ---- writeback (off critical path; released by NEXT arrive) ----
        {
            float hv = hstage[b2 * 33 + s2];
            float cv = cstage[b2 * 33 + s2];
            const size_t o = (size_t)t * NH + (B + b2) * H + r32 + s2;
            __stcg(&g_hst[o], hv);
            __stcg(&g_cst[o], cv);
            if (t == D - 1) {
                out[(B + b2) * H + r32 + s2]      = cv;   // cells
                out[NH + (B + b2) * H + r32 + s2] = hv;   // embeddings
            }
        }

        liA = liB; liB = liC; labB = labC;
        cl = cln;
#pragma unroll
        for (int g = 0; g < 5; g++) tab5[g] = t5n[g];
        cur ^= 1;
    }

    asm volatile("barrier.cluster.arrive.aligned;" ::: "memory");
    asm volatile("barrier.cluster.wait.aligned;" ::: "memory");
}

// ============================================================
extern "C" void kernel_launch(void* const* d_in, const int* in_sizes, int n_in,
                              void* d_out, int out_size) {
    const int*   trans  = (const int*)d_in[0];
    const int*   labels = (const int*)d_in[1];
    const float* emb    = (const float*)d_in[2];
    const float* W      = (const float*)d_in[3];
    const float* bias   = (const float*)d_in[4];
    const float* leaf   = (const float*)d_in[5];
    float* out = (float*)d_out;

    cudaFuncSetAttribute(k_pre, cudaFuncAttributeMaxDynamicSharedMemorySize,
                         64 * 33 * 4 + 64 * 160 * 4);
    cudaFuncSetAttribute(k_main, cudaFuncAttributeMaxDynamicSharedMemorySize,
                         SM_TOT);

    dim3 pgrid(NV / 32, 5);
    k_pre<<<pgrid, 256, 64 * 33 * 4 + 64 * 160 * 4>>>(emb, W, bias, trans);
    k_main<<<148, 256, SM_TOT>>>(labels, W, leaf, out);   // 37 clusters, 32 active
}